// round 4
// baseline (speedup 1.0000x reference)
#include <cuda_runtime.h>
#include <cmath>
#include <cstring>
#include <complex>
#include <algorithm>

// ---------------------------------------------------------------------------
// FullTensorProductSparse: irreps_in1 = 64x0e + 64x1o, irreps_in2 = 1x0e + 1x1o
// Output layout per row (1024 floats), after e3nn sort-inverse:
//   [   0:  64)  path0: 0e x 0e -> 0e            (64)
//   [  64: 128)  path3: 1o x 1o -> 0e            (64)
//   [ 128: 320)  path1: 0e x 1o -> 1o  [u,k]     (64*3)
//   [ 320: 512)  path2: 1o x 0e -> 1o  [u,k]     (64*3)
//   [ 512: 704)  path4: 1o x 1o -> 1e  [u,k]     (64*3)
//   [ 704:1024)  path5: 1o x 1o -> 2e  [u,k]     (64*5)
// ---------------------------------------------------------------------------

struct CGTables {
    float c000;            // w3j(0,0,0) * sqrt(1)
    float cg011[3][3];     // [j][k] : w3j(0,1,1)[0,j,k] * sqrt(3)
    float cg101[3][3];     // [i][k] : w3j(1,0,1)[i,0,k] * sqrt(3)
    float cg110[3][3];     // [i][j] : w3j(1,1,0)[i,j,0] * sqrt(1)
    float cg111[3][3][3];  // [i][j][k] : w3j(1,1,1) * sqrt(3)
    float cg112[3][3][5];  // [i][j][k] : w3j(1,1,2) * sqrt(5)
};

// ---------------------------------------------------------------------------
// Host-side exact reimplementation of the reference Wigner-3j construction
// (Racah formula + real<->complex spherical-harmonic basis change, e3nn
// convention) in double precision. Tiny one-time cost per launch; avoids any
// hand-derived sign/convention errors.
// ---------------------------------------------------------------------------

static double factd(int n) { double r = 1.0; for (int i = 2; i <= n; i++) r *= (double)i; return r; }

// cg[j1+m1][j2+m2][j3+m3], dims up to 5
static void su2_cg_host(int j1, int j2, int j3, double cg[5][5][5]) {
    memset(cg, 0, sizeof(double) * 5 * 5 * 5);
    for (int m1 = -j1; m1 <= j1; m1++) {
        for (int m2 = -j2; m2 <= j2; m2++) {
            int m3 = m1 + m2;
            if (m3 < -j3 || m3 > j3) continue;
            int vmin = std::max(std::max(-j1 + j2 + m3, -j1 + m1), 0);
            int vmax = std::min(std::min(j2 + j3 + m1, j3 - j1 + j2), j3 + m3);
            if (vmax < vmin) continue;
            double C = std::sqrt(
                (2.0 * j3 + 1.0)
                * factd(j3 + j1 - j2) * factd(j3 - j1 + j2) * factd(j1 + j2 - j3)
                * factd(j3 + m3) * factd(j3 - m3)
                / (factd(j1 + j2 + j3 + 1) * factd(j1 - m1) * factd(j1 + m1)
                   * factd(j2 - m2) * factd(j2 + m2)));
            double S = 0.0;
            for (int v = vmin; v <= vmax; v++) {
                double sgn = ((v + j2 + m2) & 1) ? -1.0 : 1.0;
                S += sgn * factd(j2 + j3 + m1 - v) * factd(j1 - m1 + v)
                     / (factd(v) * factd(j3 - j1 + j2 - v) * factd(j3 + m3 - v)
                        * factd(v + j1 - j2 - m3));
            }
            cg[j1 + m1][j2 + m2][j3 + m3] = C * S;
        }
    }
}

static void qmat_host(int l, std::complex<double> q[5][5]) {
    for (int a = 0; a < 5; a++) for (int b = 0; b < 5; b++) q[a][b] = 0.0;
    double r2 = std::sqrt(2.0);
    for (int m = -l; m < 0; m++) {
        q[l + m][l - m] = 1.0 / r2;                                 // col l+|m|
        q[l + m][l + m] = std::complex<double>(0.0, -1.0 / r2);     // col l-|m|
    }
    q[l][l] = 1.0;
    for (int m = 1; m <= l; m++) {
        double sgn = (m & 1) ? -1.0 : 1.0;
        q[l + m][l + m] = sgn / r2;                                 // col l+|m|
        q[l + m][l - m] = std::complex<double>(0.0, sgn / r2);      // col l-|m|
    }
    // multiply by (-i)^l
    std::complex<double> f(1.0, 0.0), mi(0.0, -1.0);
    for (int i = 0; i < l; i++) f *= mi;
    for (int a = 0; a < 2 * l + 1; a++)
        for (int b = 0; b < 2 * l + 1; b++)
            q[a][b] *= f;
}

// out[j][l][m], dims (2l1+1)(2l2+1)(2l3+1), unit Frobenius norm
static void wigner3j_host(int l1, int l2, int l3, double out[5][5][5]) {
    double cg[5][5][5];
    su2_cg_host(l1, l2, l3, cg);
    std::complex<double> Q1[5][5], Q2[5][5], Q3[5][5];
    qmat_host(l1, Q1); qmat_host(l2, Q2); qmat_host(l3, Q3);
    int d1 = 2 * l1 + 1, d2 = 2 * l2 + 1, d3 = 2 * l3 + 1;
    double norm2 = 0.0;
    for (int j = 0; j < d1; j++)
        for (int l = 0; l < d2; l++)
            for (int m = 0; m < d3; m++) {
                std::complex<double> acc(0.0, 0.0);
                for (int i = 0; i < d1; i++)
                    for (int k = 0; k < d2; k++)
                        for (int n = 0; n < d3; n++)
                            acc += Q1[i][j] * Q2[k][l] * std::conj(Q3[n][m]) * cg[i][k][n];
                out[j][l][m] = acc.real();
                norm2 += out[j][l][m] * out[j][l][m];
            }
    double inv = 1.0 / std::sqrt(norm2);
    for (int j = 0; j < d1; j++)
        for (int l = 0; l < d2; l++)
            for (int m = 0; m < d3; m++)
                out[j][l][m] *= inv;
}

static void build_tables(CGTables& T) {
    double w[5][5][5];
    double s3 = std::sqrt(3.0), s5 = std::sqrt(5.0);

    wigner3j_host(0, 0, 0, w);
    T.c000 = (float)(w[0][0][0]);   // * sqrt(1)

    wigner3j_host(0, 1, 1, w);
    for (int j = 0; j < 3; j++) for (int k = 0; k < 3; k++)
        T.cg011[j][k] = (float)(w[0][j][k] * s3);

    wigner3j_host(1, 0, 1, w);
    for (int i = 0; i < 3; i++) for (int k = 0; k < 3; k++)
        T.cg101[i][k] = (float)(w[i][0][k] * s3);

    wigner3j_host(1, 1, 0, w);
    for (int i = 0; i < 3; i++) for (int j = 0; j < 3; j++)
        T.cg110[i][j] = (float)(w[i][j][0]);  // * sqrt(1)

    wigner3j_host(1, 1, 1, w);
    for (int i = 0; i < 3; i++) for (int j = 0; j < 3; j++) for (int k = 0; k < 3; k++)
        T.cg111[i][j][k] = (float)(w[i][j][k] * s3);

    wigner3j_host(1, 1, 2, w);
    for (int i = 0; i < 3; i++) for (int j = 0; j < 3; j++) for (int k = 0; k < 5; k++)
        T.cg112[i][j][k] = (float)(w[i][j][k] * s5);
}

// ---------------------------------------------------------------------------
// Kernel: one thread per (row, channel u). 64 threads/row, 4 rows per
// 256-thread block. Results staged in shared memory, then written to GMEM as
// fully-coalesced float4 stores (4 x STG.128 per thread).
//
// Smem bank analysis for the staging writes: per-warp address strides within
// sbuf are 1 (paths 0/3), 3 (paths 1/2/4) and 5 (path 5); all coprime with
// the 32-bank crossbar -> conflict-free. The float4 readback is 512B
// contiguous per warp -> conflict-free 4-phase.
// ---------------------------------------------------------------------------

__global__ void __launch_bounds__(256)
tp_kernel(const float* __restrict__ in1,
          const float* __restrict__ in2,
          float* __restrict__ out,
          int N, CGTables T)
{
    __shared__ float sbuf[4 * 1024];   // 4 rows x 1024 outputs = 16 KB

    int tid = blockIdx.x * blockDim.x + threadIdx.x;
    int row = tid >> 6;          // global row
    int u   = tid & 63;          // channel
    int rloc = threadIdx.x >> 6; // row within block (0..3)
    bool active = (row < N);

    if (active) {
        const float* r1 = in1 + (size_t)row * 256;
        const float* r2 = in2 + (size_t)row * 4;

        float s1 = r1[u];
        float v1[3];
#pragma unroll
        for (int i = 0; i < 3; i++) v1[i] = r1[64 + u * 3 + i];

        float s2 = r2[0];
        float v2[3];
#pragma unroll
        for (int j = 0; j < 3; j++) v2[j] = r2[1 + j];

        float* o = sbuf + rloc * 1024;

        // path0: 0e x 0e -> 0e
        o[u] = T.c000 * s1 * s2;

        // path3: 1o x 1o -> 0e
        {
            float acc = 0.f;
#pragma unroll
            for (int i = 0; i < 3; i++)
#pragma unroll
                for (int j = 0; j < 3; j++)
                    acc += v1[i] * v2[j] * T.cg110[i][j];
            o[64 + u] = acc;
        }

        // path1: 0e x 1o -> 1o
#pragma unroll
        for (int k = 0; k < 3; k++) {
            float t = 0.f;
#pragma unroll
            for (int j = 0; j < 3; j++) t += v2[j] * T.cg011[j][k];
            o[128 + u * 3 + k] = s1 * t;
        }

        // path2: 1o x 0e -> 1o
#pragma unroll
        for (int k = 0; k < 3; k++) {
            float t = 0.f;
#pragma unroll
            for (int i = 0; i < 3; i++) t += v1[i] * T.cg101[i][k];
            o[320 + u * 3 + k] = s2 * t;
        }

        // path4: 1o x 1o -> 1e
#pragma unroll
        for (int k = 0; k < 3; k++) {
            float t = 0.f;
#pragma unroll
            for (int i = 0; i < 3; i++)
#pragma unroll
                for (int j = 0; j < 3; j++)
                    t += v1[i] * v2[j] * T.cg111[i][j][k];
            o[512 + u * 3 + k] = t;
        }

        // path5: 1o x 1o -> 2e
#pragma unroll
        for (int k = 0; k < 5; k++) {
            float t = 0.f;
#pragma unroll
            for (int i = 0; i < 3; i++)
#pragma unroll
                for (int j = 0; j < 3; j++)
                    t += v1[i] * v2[j] * T.cg112[i][j][k];
            o[704 + u * 5 + k] = t;
        }
    }

    __syncthreads();

    // Coalesced writeback: this block owns rows [blockRow0, blockRow0+4),
    // i.e. 4096 contiguous output floats = 1024 float4.
    int blockRow0 = (blockIdx.x * blockDim.x) >> 6;
    size_t baseElem = (size_t)blockRow0 * 1024;
    int rowsInBlock = min(4, N - blockRow0);
    if (rowsInBlock >= 4) {
        // fast path: 4 full rows
        float4* __restrict__ dst = (float4*)(out + baseElem);
        const float4* __restrict__ src = (const float4*)sbuf;
#pragma unroll
        for (int it = 0; it < 4; it++)
            dst[threadIdx.x + it * 256] = src[threadIdx.x + it * 256];
    } else if (rowsInBlock > 0) {
        int nvec = rowsInBlock * 256;           // float4 count
        float4* __restrict__ dst = (float4*)(out + baseElem);
        const float4* __restrict__ src = (const float4*)sbuf;
        for (int idx = threadIdx.x; idx < nvec; idx += 256)
            dst[idx] = src[idx];
    }
}

extern "C" void kernel_launch(void* const* d_in, const int* in_sizes, int n_in,
                              void* d_out, int out_size)
{
    const float* in1 = (const float*)d_in[0];   // [N, 256]
    const float* in2 = (const float*)d_in[1];   // [N, 4]
    float* out = (float*)d_out;                 // [N, 1024]
    int N = in_sizes[0] / 256;

    CGTables T;
    build_tables(T);

    int threads = 256;                 // 4 rows per block
    int total = N * 64;
    int blocks = (total + threads - 1) / threads;
    tp_kernel<<<blocks, threads>>>(in1, in2, out, N, T);
}

// round 10
// speedup vs baseline: 1.0671x; 1.0671x over previous
#include <cuda_runtime.h>
#include <cmath>
#include <cstring>
#include <complex>
#include <algorithm>

// ---------------------------------------------------------------------------
// FullTensorProductSparse: irreps_in1 = 64x0e + 64x1o, irreps_in2 = 1x0e + 1x1o
// Output layout per row (1024 floats), after e3nn sort-inverse:
//   [   0:  64)  path0: 0e x 0e -> 0e            (64)
//   [  64: 128)  path3: 1o x 1o -> 0e            (64)
//   [ 128: 320)  path1: 0e x 1o -> 1o  [u,k]     (64*3)
//   [ 320: 512)  path2: 1o x 0e -> 1o  [u,k]     (64*3)
//   [ 512: 704)  path4: 1o x 1o -> 1e  [u,k]     (64*3)
//   [ 704:1024)  path5: 1o x 1o -> 2e  [u,k]     (64*5)
//
// Round-5 design: ONE WARP PER ROW (2 channels/thread), warp-private smem
// staging, __syncwarp only (no block barrier), streaming STG.128 writeback.
// ---------------------------------------------------------------------------

struct CGTables {
    float c000;            // w3j(0,0,0) * sqrt(1)
    float cg011[3][3];     // [j][k] : w3j(0,1,1)[0,j,k] * sqrt(3)
    float cg101[3][3];     // [i][k] : w3j(1,0,1)[i,0,k] * sqrt(3)
    float cg110[3][3];     // [i][j] : w3j(1,1,0)[i,j,0] * sqrt(1)
    float cg111[3][3][3];  // [i][j][k] : w3j(1,1,1) * sqrt(3)
    float cg112[3][3][5];  // [i][j][k] : w3j(1,1,2) * sqrt(5)
};

// ---------------------------------------------------------------------------
// Host-side exact reimplementation of the reference Wigner-3j construction
// (Racah formula + real<->complex spherical-harmonic basis change, e3nn
// convention) in double precision.
// ---------------------------------------------------------------------------

static double factd(int n) { double r = 1.0; for (int i = 2; i <= n; i++) r *= (double)i; return r; }

static void su2_cg_host(int j1, int j2, int j3, double cg[5][5][5]) {
    memset(cg, 0, sizeof(double) * 5 * 5 * 5);
    for (int m1 = -j1; m1 <= j1; m1++) {
        for (int m2 = -j2; m2 <= j2; m2++) {
            int m3 = m1 + m2;
            if (m3 < -j3 || m3 > j3) continue;
            int vmin = std::max(std::max(-j1 + j2 + m3, -j1 + m1), 0);
            int vmax = std::min(std::min(j2 + j3 + m1, j3 - j1 + j2), j3 + m3);
            if (vmax < vmin) continue;
            double C = std::sqrt(
                (2.0 * j3 + 1.0)
                * factd(j3 + j1 - j2) * factd(j3 - j1 + j2) * factd(j1 + j2 - j3)
                * factd(j3 + m3) * factd(j3 - m3)
                / (factd(j1 + j2 + j3 + 1) * factd(j1 - m1) * factd(j1 + m1)
                   * factd(j2 - m2) * factd(j2 + m2)));
            double S = 0.0;
            for (int v = vmin; v <= vmax; v++) {
                double sgn = ((v + j2 + m2) & 1) ? -1.0 : 1.0;
                S += sgn * factd(j2 + j3 + m1 - v) * factd(j1 - m1 + v)
                     / (factd(v) * factd(j3 - j1 + j2 - v) * factd(j3 + m3 - v)
                        * factd(v + j1 - j2 - m3));
            }
            cg[j1 + m1][j2 + m2][j3 + m3] = C * S;
        }
    }
}

static void qmat_host(int l, std::complex<double> q[5][5]) {
    for (int a = 0; a < 5; a++) for (int b = 0; b < 5; b++) q[a][b] = 0.0;
    double r2 = std::sqrt(2.0);
    for (int m = -l; m < 0; m++) {
        q[l + m][l - m] = 1.0 / r2;
        q[l + m][l + m] = std::complex<double>(0.0, -1.0 / r2);
    }
    q[l][l] = 1.0;
    for (int m = 1; m <= l; m++) {
        double sgn = (m & 1) ? -1.0 : 1.0;
        q[l + m][l + m] = sgn / r2;
        q[l + m][l - m] = std::complex<double>(0.0, sgn / r2);
    }
    std::complex<double> f(1.0, 0.0), mi(0.0, -1.0);
    for (int i = 0; i < l; i++) f *= mi;
    for (int a = 0; a < 2 * l + 1; a++)
        for (int b = 0; b < 2 * l + 1; b++)
            q[a][b] *= f;
}

static void wigner3j_host(int l1, int l2, int l3, double out[5][5][5]) {
    double cg[5][5][5];
    su2_cg_host(l1, l2, l3, cg);
    std::complex<double> Q1[5][5], Q2[5][5], Q3[5][5];
    qmat_host(l1, Q1); qmat_host(l2, Q2); qmat_host(l3, Q3);
    int d1 = 2 * l1 + 1, d2 = 2 * l2 + 1, d3 = 2 * l3 + 1;
    double norm2 = 0.0;
    for (int j = 0; j < d1; j++)
        for (int l = 0; l < d2; l++)
            for (int m = 0; m < d3; m++) {
                std::complex<double> acc(0.0, 0.0);
                for (int i = 0; i < d1; i++)
                    for (int k = 0; k < d2; k++)
                        for (int n = 0; n < d3; n++)
                            acc += Q1[i][j] * Q2[k][l] * std::conj(Q3[n][m]) * cg[i][k][n];
                out[j][l][m] = acc.real();
                norm2 += out[j][l][m] * out[j][l][m];
            }
    double inv = 1.0 / std::sqrt(norm2);
    for (int j = 0; j < d1; j++)
        for (int l = 0; l < d2; l++)
            for (int m = 0; m < d3; m++)
                out[j][l][m] *= inv;
}

static void build_tables(CGTables& T) {
    double w[5][5][5];
    double s3 = std::sqrt(3.0), s5 = std::sqrt(5.0);

    wigner3j_host(0, 0, 0, w);
    T.c000 = (float)(w[0][0][0]);

    wigner3j_host(0, 1, 1, w);
    for (int j = 0; j < 3; j++) for (int k = 0; k < 3; k++)
        T.cg011[j][k] = (float)(w[0][j][k] * s3);

    wigner3j_host(1, 0, 1, w);
    for (int i = 0; i < 3; i++) for (int k = 0; k < 3; k++)
        T.cg101[i][k] = (float)(w[i][0][k] * s3);

    wigner3j_host(1, 1, 0, w);
    for (int i = 0; i < 3; i++) for (int j = 0; j < 3; j++)
        T.cg110[i][j] = (float)(w[i][j][0]);

    wigner3j_host(1, 1, 1, w);
    for (int i = 0; i < 3; i++) for (int j = 0; j < 3; j++) for (int k = 0; k < 3; k++)
        T.cg111[i][j][k] = (float)(w[i][j][k] * s3);

    wigner3j_host(1, 1, 2, w);
    for (int i = 0; i < 3; i++) for (int j = 0; j < 3; j++) for (int k = 0; k < 5; k++)
        T.cg112[i][j][k] = (float)(w[i][j][k] * s5);
}

// ---------------------------------------------------------------------------
// Kernel: one WARP per row; each thread handles channels u = lane and lane+32.
// Row outputs staged in a warp-private 4KB smem slice (conflict-free: staging
// strides 1/3/5 are coprime with 32 banks), then written back as 8 x STG.128
// per thread with streaming (.cs) hint. No block-wide synchronization.
// ---------------------------------------------------------------------------

#define WARPS_PER_BLOCK 8

__global__ void __launch_bounds__(32 * WARPS_PER_BLOCK)
tp_kernel(const float* __restrict__ in1,
          const float* __restrict__ in2,
          float* __restrict__ out,
          int N, CGTables T)
{
    __shared__ float sbuf[WARPS_PER_BLOCK * 1024];   // 4KB per warp

    int lane = threadIdx.x & 31;
    int wloc = threadIdx.x >> 5;
    int row  = blockIdx.x * WARPS_PER_BLOCK + wloc;
    if (row >= N) return;   // warp-uniform

    const float* r1 = in1 + (size_t)row * 256;
    const float* r2 = in2 + (size_t)row * 4;

    // in2 is warp-uniform (broadcast through L1)
    float s2 = r2[0];
    float v2[3];
#pragma unroll
    for (int j = 0; j < 3; j++) v2[j] = r2[1 + j];

    float* o = sbuf + wloc * 1024;

#pragma unroll
    for (int c = 0; c < 2; c++) {
        int u = lane + 32 * c;

        float s1 = __ldcs(&r1[u]);
        float v1[3];
#pragma unroll
        for (int i = 0; i < 3; i++) v1[i] = __ldcs(&r1[64 + u * 3 + i]);

        // path0: 0e x 0e -> 0e
        o[u] = T.c000 * s1 * s2;

        // path3: 1o x 1o -> 0e
        {
            float acc = 0.f;
#pragma unroll
            for (int i = 0; i < 3; i++)
#pragma unroll
                for (int j = 0; j < 3; j++)
                    acc += v1[i] * v2[j] * T.cg110[i][j];
            o[64 + u] = acc;
        }

        // path1: 0e x 1o -> 1o
#pragma unroll
        for (int k = 0; k < 3; k++) {
            float t = 0.f;
#pragma unroll
            for (int j = 0; j < 3; j++) t += v2[j] * T.cg011[j][k];
            o[128 + u * 3 + k] = s1 * t;
        }

        // path2: 1o x 0e -> 1o
#pragma unroll
        for (int k = 0; k < 3; k++) {
            float t = 0.f;
#pragma unroll
            for (int i = 0; i < 3; i++) t += v1[i] * T.cg101[i][k];
            o[320 + u * 3 + k] = s2 * t;
        }

        // path4: 1o x 1o -> 1e
#pragma unroll
        for (int k = 0; k < 3; k++) {
            float t = 0.f;
#pragma unroll
            for (int i = 0; i < 3; i++)
#pragma unroll
                for (int j = 0; j < 3; j++)
                    t += v1[i] * v2[j] * T.cg111[i][j][k];
            o[512 + u * 3 + k] = t;
        }

        // path5: 1o x 1o -> 2e
#pragma unroll
        for (int k = 0; k < 5; k++) {
            float t = 0.f;
#pragma unroll
            for (int i = 0; i < 3; i++)
#pragma unroll
                for (int j = 0; j < 3; j++)
                    t += v1[i] * v2[j] * T.cg112[i][j][k];
            o[704 + u * 5 + k] = t;
        }
    }

    __syncwarp();

    // Coalesced streaming writeback: 1024 floats = 256 float4, 8 per lane.
    float4* __restrict__ dst = (float4*)(out + (size_t)row * 1024);
    const float4* __restrict__ src = (const float4*)o;
#pragma unroll
    for (int it = 0; it < 8; it++)
        __stcs(&dst[lane + it * 32], src[lane + it * 32]);
}

extern "C" void kernel_launch(void* const* d_in, const int* in_sizes, int n_in,
                              void* d_out, int out_size)
{
    const float* in1 = (const float*)d_in[0];   // [N, 256]
    const float* in2 = (const float*)d_in[1];   // [N, 4]
    float* out = (float*)d_out;                 // [N, 1024]
    int N = in_sizes[0] / 256;

    CGTables T;
    build_tables(T);

    int blocks = (N + WARPS_PER_BLOCK - 1) / WARPS_PER_BLOCK;
    tp_kernel<<<blocks, 32 * WARPS_PER_BLOCK>>>(in1, in2, out, N, T);
}